// round 5
// baseline (speedup 1.0000x reference)
#include <cuda_runtime.h>
#include <cuda_bf16.h>
#include <cstdint>

// DepthToSpace, BLOCK_SIZE=2
// in : x   (B=16, C=256, H=128, W=128) fp32
// out:     (B=16, d=64,  H2=256, W2=256) fp32
//
// out[b, dd, h*2+i, w*2+k] = x[b, (i*2+k)*64 + dd, h, w]
//
// For a fixed output row (b, dd, ho): i = ho&1, h = ho>>1.
//   even wo come from channel c0 = i*128 + dd        (contiguous in w)
//   odd  wo come from channel c1 = i*128 + 64 + dd   (contiguous in w)
//
// R3 design, third bench attempt (two infra failures): 64B per thread each
// direction. Each thread issues 4 independent LDG.128 (two consecutive
// float4 from each source row) and 4 independent STG.128 covering 16
// consecutive output floats. All accesses fully coalesced; streaming
// cache policy (zero reuse).

#define W_IN      128
#define H_IN      128
#define C_IN      256
#define D_OUT     64
#define CH_STRIDE (H_IN * W_IN)          // 16384 floats per input channel
#define SEG_PER_ROW 16                   // 256 out floats = 16 segments of 16
#define N_ROWS    (16 * D_OUT * 256)     // 262144 output rows
#define N_THREADS (N_ROWS * SEG_PER_ROW) // 4,194,304

__global__ void __launch_bounds__(256)
d2s_kernel(const float4* __restrict__ x4, float4* __restrict__ out4) {
    unsigned tid = blockIdx.x * blockDim.x + threadIdx.x;

    unsigned j   = tid & (SEG_PER_ROW - 1); // segment within output row (0..15)
    unsigned row = tid >> 4;                // global output row (0..262143)

    unsigned ho = row & 255;                // output height index
    unsigned dd = (row >> 8) & (D_OUT - 1);
    unsigned b  = row >> 14;

    unsigned i = ho & 1;
    unsigned h = ho >> 1;

    // float4 base index into x for (b, c0, h, 0):  c0 = i*128 + dd
    size_t base4 = ((((size_t)b * C_IN + i * 128u + dd) * H_IN + h) * W_IN) >> 2;
    size_t a_idx = base4 + 2u * j;                          // c0, w = 8j..8j+7
    size_t c_idx = a_idx + (size_t)(64 * CH_STRIDE / 4);    // c1, same w

    // 4 independent loads, front-batched
    float4 a0 = __ldcs(&x4[a_idx]);
    float4 c0 = __ldcs(&x4[c_idx]);
    float4 a1 = __ldcs(&x4[a_idx + 1]);
    float4 c1 = __ldcs(&x4[c_idx + 1]);

    // output row `row`, float4 slots 4j..4j+3: wo = 16j..16j+15
    size_t o = (size_t)row * (SEG_PER_ROW * 4) + 4u * j;
    __stcs(&out4[o],     make_float4(a0.x, c0.x, a0.y, c0.y));
    __stcs(&out4[o + 1], make_float4(a0.z, c0.z, a0.w, c0.w));
    __stcs(&out4[o + 2], make_float4(a1.x, c1.x, a1.y, c1.y));
    __stcs(&out4[o + 3], make_float4(a1.z, c1.z, a1.w, c1.w));
}

extern "C" void kernel_launch(void* const* d_in, const int* in_sizes, int n_in,
                              void* d_out, int out_size) {
    const float4* x4   = (const float4*)d_in[0];
    float4*       out4 = (float4*)d_out;

    // 4,194,304 threads / 256 = 16384 blocks, exact (no tail predicate needed)
    d2s_kernel<<<N_THREADS / 256, 256>>>(x4, out4);
}

// round 6
// speedup vs baseline: 1.0766x; 1.0766x over previous
#include <cuda_runtime.h>
#include <cuda_bf16.h>
#include <cstdint>

// DepthToSpace, BLOCK_SIZE=2
// in : x   (B=16, C=256, H=128, W=128) fp32
// out:     (B=16, d=64,  H2=256, W2=256) fp32
//
// out[b, dd, h*2+i, w*2+k] = x[b, (i*2+k)*64 + dd, h, w]
//
// For a fixed output row (b, dd, ho): i = ho&1, h = ho>>1.
//   even wo come from channel c0 = i*128 + dd        (contiguous in w)
//   odd  wo come from channel c1 = i*128 + 64 + dd   (contiguous in w)
//
// R6: R2's lane geometry (dense loads / half-dense stores — proven best)
// widened to Blackwell 256-bit vector accesses (ld/st.global.v8.b32,
// sm_100a). Thread j: one v8 (32B) from each source row at v8-index j
// (dense across lanes, 32B-aligned), two v8 stores to out-slots 2j, 2j+1.
// 16 threads per output row.

#define W_IN      128
#define H_IN      128
#define C_IN      256
#define D_OUT     64
#define CH_STRIDE (H_IN * W_IN)            // 16384 floats per input channel
#define V8_PER_ROW_IN  16                  // 128 in floats per row = 16 v8
#define N_ROWS    (16 * D_OUT * 256)       // 262144 output rows
#define N_THREADS (N_ROWS * V8_PER_ROW_IN) // 4,194,304

__device__ __forceinline__ void ldg_v8(const float* p, float v[8]) {
    asm volatile(
        "ld.global.v8.b32 {%0,%1,%2,%3,%4,%5,%6,%7}, [%8];"
        : "=f"(v[0]), "=f"(v[1]), "=f"(v[2]), "=f"(v[3]),
          "=f"(v[4]), "=f"(v[5]), "=f"(v[6]), "=f"(v[7])
        : "l"(p));
}

__device__ __forceinline__ void stg_v8(float* p, float a0, float a1, float a2, float a3,
                                                 float a4, float a5, float a6, float a7) {
    asm volatile(
        "st.global.v8.b32 [%0], {%1,%2,%3,%4,%5,%6,%7,%8};"
        :: "l"(p),
           "f"(a0), "f"(a1), "f"(a2), "f"(a3),
           "f"(a4), "f"(a5), "f"(a6), "f"(a7)
        : "memory");
}

__global__ void __launch_bounds__(256)
d2s_kernel(const float* __restrict__ x, float* __restrict__ out) {
    unsigned tid = blockIdx.x * blockDim.x + threadIdx.x;

    unsigned j   = tid & (V8_PER_ROW_IN - 1); // v8 index within input row (0..15)
    unsigned row = tid >> 4;                  // global output row (0..262143)

    unsigned ho = row & 255;                  // output height index
    unsigned dd = (row >> 8) & (D_OUT - 1);
    unsigned b  = row >> 14;

    unsigned i = ho & 1;
    unsigned h = ho >> 1;

    // float base index into x for (b, c0, h, 0):  c0 = i*128 + dd
    size_t base = (((size_t)b * C_IN + i * 128u + dd) * H_IN + h) * W_IN;

    float a[8], c[8];
    ldg_v8(&x[base + 8u * j], a);                               // c0, w = 8j..8j+7
    ldg_v8(&x[base + (size_t)(64 * CH_STRIDE) + 8u * j], c);    // c1, same w

    // output row `row`, floats 16j..16j+15 = a0,c0,a1,c1,...,a7,c7
    float* o = &out[(size_t)row * 256 + 16u * j];
    stg_v8(o,     a[0], c[0], a[1], c[1], a[2], c[2], a[3], c[3]);
    stg_v8(o + 8, a[4], c[4], a[5], c[5], a[6], c[6], a[7], c[7]);
}

extern "C" void kernel_launch(void* const* d_in, const int* in_sizes, int n_in,
                              void* d_out, int out_size) {
    const float* x   = (const float*)d_in[0];
    float*       out = (float*)d_out;

    // 4,194,304 threads / 256 = 16384 blocks, exact (no tail predicate needed)
    d2s_kernel<<<N_THREADS / 256, 256>>>(x, out);
}

// round 7
// speedup vs baseline: 1.0770x; 1.0004x over previous
#include <cuda_runtime.h>
#include <cuda_bf16.h>
#include <cstdint>

// DepthToSpace, BLOCK_SIZE=2
// in : x   (B=16, C=256, H=128, W=128) fp32
// out:     (B=16, d=64,  H2=256, W2=256) fp32
//
// out[b, dd, h*2+i, w*2+k] = x[b, (i*2+k)*64 + dd, h, w]
//
// R7: row-pair per thread + streaming (.cs) 256-bit vector accesses.
// For fixed (b, dd, m), output rows ho=2m (i=0) and ho=2m+1 (i=1) pull
// from input channels {dd, 64+dd} and {128+dd, 192+dd} respectively, all
// at height m. Thread j loads one v8 (32B) from each of the 4 channel
// rows at dense v8-offset j (fully coalesced across lanes), and writes
// 4 v8 covering floats 16j..16j+15 of both output rows.

#define W_IN      128
#define H_IN      128
#define C_IN      256
#define D_OUT     64
#define CH_STRIDE (H_IN * W_IN)            // 16384 floats per input channel
#define V8_PER_ROW_IN  16                  // 128 in floats per row = 16 v8
#define N_THREADS (16 * D_OUT * 128 * V8_PER_ROW_IN) // b*dd*m*j = 2,097,152

__device__ __forceinline__ void ldg_v8_cs(const float* p, float v[8]) {
    asm volatile(
        "ld.global.cs.v8.b32 {%0,%1,%2,%3,%4,%5,%6,%7}, [%8];"
        : "=f"(v[0]), "=f"(v[1]), "=f"(v[2]), "=f"(v[3]),
          "=f"(v[4]), "=f"(v[5]), "=f"(v[6]), "=f"(v[7])
        : "l"(p));
}

__device__ __forceinline__ void stg_v8_cs(float* p, float a0, float a1, float a2, float a3,
                                                    float a4, float a5, float a6, float a7) {
    asm volatile(
        "st.global.cs.v8.b32 [%0], {%1,%2,%3,%4,%5,%6,%7,%8};"
        :: "l"(p),
           "f"(a0), "f"(a1), "f"(a2), "f"(a3),
           "f"(a4), "f"(a5), "f"(a6), "f"(a7)
        : "memory");
}

__global__ void __launch_bounds__(256)
d2s_kernel(const float* __restrict__ x, float* __restrict__ out) {
    unsigned tid = blockIdx.x * blockDim.x + threadIdx.x;

    unsigned j  = tid & (V8_PER_ROW_IN - 1); // v8 index within input row (0..15)
    unsigned r  = tid >> 4;
    unsigned m  = r & (H_IN - 1);            // input height (0..127)
    unsigned r2 = r >> 7;
    unsigned dd = r2 & (D_OUT - 1);
    unsigned b  = r2 >> 6;

    // input row base for (b, ch, m): ((b*256 + ch)*128 + m)*128
    size_t base_dd = (((size_t)b * C_IN + dd) * H_IN + m) * W_IN + 8u * j;

    float a0[8], c0[8], a1[8], c1[8];
    ldg_v8_cs(&x[base_dd                            ], a0); // ch = dd       (i=0,k=0)
    ldg_v8_cs(&x[base_dd + (size_t) 64 * CH_STRIDE  ], c0); // ch = 64+dd    (i=0,k=1)
    ldg_v8_cs(&x[base_dd + (size_t)128 * CH_STRIDE  ], a1); // ch = 128+dd   (i=1,k=0)
    ldg_v8_cs(&x[base_dd + (size_t)192 * CH_STRIDE  ], c1); // ch = 192+dd   (i=1,k=1)

    // output rows r0 = (b*64+dd)*256 + 2m  and  r0+1
    size_t r0 = ((size_t)b * D_OUT + dd) * 256 + 2u * m;
    float* o0 = &out[r0 * 256 + 16u * j];
    float* o1 = o0 + 256;

    stg_v8_cs(o0,     a0[0], c0[0], a0[1], c0[1], a0[2], c0[2], a0[3], c0[3]);
    stg_v8_cs(o0 + 8, a0[4], c0[4], a0[5], c0[5], a0[6], c0[6], a0[7], c0[7]);
    stg_v8_cs(o1,     a1[0], c1[0], a1[1], c1[1], a1[2], c1[2], a1[3], c1[3]);
    stg_v8_cs(o1 + 8, a1[4], c1[4], a1[5], c1[5], a1[6], c1[6], a1[7], c1[7]);
}

extern "C" void kernel_launch(void* const* d_in, const int* in_sizes, int n_in,
                              void* d_out, int out_size) {
    const float* x   = (const float*)d_in[0];
    float*       out = (float*)d_out;

    // 2,097,152 threads / 256 = 8192 blocks, exact (no tail predicate needed)
    d2s_kernel<<<N_THREADS / 256, 256>>>(x, out);
}